// round 16
// baseline (speedup 1.0000x reference)
#include <cuda_runtime.h>
#include <cuda_bf16.h>
#include <cstdint>

#define Nn 4096
#define Bb 4
#define Cc 128
#define Hh 8
#define Vv 16
#define HV 128

// ---------------- static device scratch ------------------------------------
// interleaved value planes: per (h, c2) row of Nn words; word 2p = {hi(2p),hi(2p+1)},
// word 2p+1 = {lo(2p),lo(2p+1)}  (bf16x2 words)
__device__ __align__(16) uint32_t g_vi[(size_t)Hh * 64 * Nn];
__device__ float g_rowstats[3 * Nn];  // [0..N) d_lo, [N..2N) d_hi, [2N..3N) d_min

__device__ __forceinline__ float read_pct(const int* p) {
    if (!p) return 64.0f;
    int v = *p;
    if (v >= 0 && v <= 100) return (float)v;
    float f = __int_as_float(v);
    if (f >= 0.0f && f <= 100.0f) return f;
    return 64.0f;
}

// warp-level bf16 tensor-core mma (sm_80+ PTX, valid on base sm_103 target)
#define MMA_BF16(c0, c1, c2, c3, a0, a1, a2, a3, b0, b1)                      \
    asm volatile(                                                             \
        "mma.sync.aligned.m16n8k16.row.col.f32.bf16.bf16.f32 "                \
        "{%0,%1,%2,%3}, {%4,%5,%6,%7}, {%8,%9}, {%0,%1,%2,%3};"               \
        : "+f"(c0), "+f"(c1), "+f"(c2), "+f"(c3)                              \
        : "r"(a0), "r"(a1), "r"(a2), "r"(a3), "r"(b0), "r"(b1))

// pack two floats -> bf16x2 (RN); flo -> low half, fhi -> high half
#define PACK_BF16X2(d, flo, fhi) \
    asm("cvt.rn.bf16x2.f32 %0, %1, %2;" : "=r"(d) : "f"(fhi), "f"(flo))

#define CP_ASYNC16(dst_u32, src_ptr) \
    asm volatile("cp.async.cg.shared.global [%0], [%1], 16;" \
                 :: "r"(dst_u32), "l"(src_ptr) : "memory")
#define CP_COMMIT() asm volatile("cp.async.commit_group;" ::: "memory")
#define CP_WAIT0()  asm volatile("cp.async.wait_group 0;" ::: "memory")

__device__ __forceinline__ uint32_t smem_u32(const void* p) {
    uint32_t a;
    asm("{ .reg .u64 t; cvta.to.shared.u64 t, %1; cvt.u32.u64 %0, t; }"
        : "=r"(a) : "l"(p));
    return a;
}

// ---------------------------------------------------------------------------
// Kernel 1: per row of dist: rank-k0 order statistic (radix select, exact,
// tie-safe on non-negative float bit patterns), rank-k0+1 from one extra
// pass, plus row min.  REGISTER-RESIDENT keys: each thread holds 16 keys in
// regs; all 5 scan passes read registers instead of smem.
// ---------------------------------------------------------------------------
__global__ void __launch_bounds__(256, 1) rowstats_kernel(
    const float* __restrict__ dist, const int* __restrict__ locp) {
    __shared__ unsigned hist[256];
    __shared__ unsigned wsums[8];
    __shared__ unsigned sb[2];
    __shared__ float smin[256];
    __shared__ unsigned s_cntLE;
    __shared__ unsigned s_minAbove;

    const int row = blockIdx.x;
    const int t = threadIdx.x;

    const float* rp = dist + (size_t)row * Nn;
    unsigned key[16];
    float mn = 3.4e38f;
    #pragma unroll
    for (int it = 0; it < 16; it++) {
        float v = rp[t + 256 * it];
        key[it] = __float_as_uint(v);
        mn = fminf(mn, v);
    }
    smin[t] = mn;
    if (t == 0) { s_cntLE = 0u; s_minAbove = 0xFFFFFFFFu; }
    __syncthreads();
    for (int s = 128; s > 0; s >>= 1) {
        if (t < s) smin[t] = fminf(smin[t], smin[t + s]);
        __syncthreads();
    }

    float pct = read_pct(locp);
    float q = pct / 100.0f;
    float fidx = q * (float)(Nn - 1);
    int k0 = (int)floorf(fidx);
    if (k0 < 0) k0 = 0;
    if (k0 > Nn - 1) k0 = Nn - 1;

    int k = k0;
    unsigned prefix = 0u, pmask = 0u;
    for (int shift = 24; shift >= 0; shift -= 8) {
        hist[t] = 0u;
        __syncthreads();
        #pragma unroll
        for (int it = 0; it < 16; it++) {
            unsigned ky = key[it];
            if ((ky & pmask) == prefix)
                atomicAdd(&hist[(ky >> shift) & 255u], 1u);
        }
        __syncthreads();
        unsigned c = hist[t];
        unsigned v = c;
        #pragma unroll
        for (int o = 1; o < 32; o <<= 1) {
            unsigned u = __shfl_up_sync(0xffffffffu, v, o);
            if ((t & 31) >= o) v += u;
        }
        if ((t & 31) == 31) wsums[t >> 5] = v;
        __syncthreads();
        if (t < 8) {
            unsigned w = wsums[t];
            #pragma unroll
            for (int o = 1; o < 8; o <<= 1) {
                unsigned u = __shfl_up_sync(0xffu, w, o);
                if (t >= o) w += u;
            }
            wsums[t] = w;
        }
        __syncthreads();
        unsigned incl = v + ((t >= 32) ? wsums[(t >> 5) - 1] : 0u);
        unsigned excl = incl - c;
        if ((unsigned)k >= excl && (unsigned)k < incl) {
            sb[0] = (unsigned)t;
            sb[1] = excl;
        }
        __syncthreads();
        prefix |= sb[0] << shift;
        pmask |= 0xFFu << shift;
        k -= (int)sb[1];
        __syncthreads();
    }
    const unsigned val0 = prefix;

    {
        unsigned lcnt = 0u, lmin = 0xFFFFFFFFu;
        #pragma unroll
        for (int it = 0; it < 16; it++) {
            unsigned ky = key[it];
            if (ky <= val0) lcnt++;
            else lmin = min(lmin, ky);
        }
        #pragma unroll
        for (int o = 16; o > 0; o >>= 1) {
            lcnt += __shfl_down_sync(0xffffffffu, lcnt, o);
            lmin = min(lmin, __shfl_down_sync(0xffffffffu, lmin, o));
        }
        if ((t & 31) == 0) {
            atomicAdd(&s_cntLE, lcnt);
            atomicMin(&s_minAbove, lmin);
        }
    }
    __syncthreads();

    if (t == 0) {
        unsigned val1;
        int k1 = (k0 + 1 < Nn) ? (k0 + 1) : (Nn - 1);
        if (k1 == k0 || (unsigned)k1 < s_cntLE) val1 = val0;
        else val1 = s_minAbove;
        g_rowstats[row] = __uint_as_float(val0);
        g_rowstats[Nn + row] = __uint_as_float(val1);
        g_rowstats[2 * Nn + row] = smin[0];
    }
}

// ---------------------------------------------------------------------------
// Kernel 2: value[h][j][c2] = sum_c inputs[b,j,c]*weight[h,c,v]  (c2=b*16+v),
// split into bf16 hi/lo (RN) and written transposed + INTERLEAVED to g_vi.
// ---------------------------------------------------------------------------
__global__ void __launch_bounds__(512, 1) value_kernel(
    const float* __restrict__ inputs, const float* __restrict__ weight) {
    __shared__ float wsm[Cc * Vv];                 // 8KB
    __shared__ __nv_bfloat16 shT[64][72];          // [c2][j] hi
    __shared__ __nv_bfloat16 slT[64][72];          // [c2][j] lo
    const int h = blockIdx.y;
    const int j0 = blockIdx.x * 64;
    const int tid = threadIdx.x;

    for (int e = tid; e < Cc * Vv; e += 512) wsm[e] = weight[h * (Cc * Vv) + e];
    __syncthreads();

    const int c2 = tid & 63;
    const int jj = tid >> 6;  // 0..7
    const int b = c2 >> 4;
    const int v = c2 & 15;

    #pragma unroll
    for (int l = 0; l < 8; l++) {
        int jl = jj + l * 8;
        int j = j0 + jl;
        const float4* ip = (const float4*)(inputs + ((size_t)b * Nn + j) * Cc);
        float acc = 0.0f;
        #pragma unroll
        for (int c4 = 0; c4 < Cc / 4; c4++) {
            float4 x = ip[c4];
            acc += x.x * wsm[(c4 * 4 + 0) * Vv + v];
            acc += x.y * wsm[(c4 * 4 + 1) * Vv + v];
            acc += x.z * wsm[(c4 * 4 + 2) * Vv + v];
            acc += x.w * wsm[(c4 * 4 + 3) * Vv + v];
        }
        __nv_bfloat16 hi = __float2bfloat16(acc);
        __nv_bfloat16 lo = __float2bfloat16(acc - __bfloat162float(hi));
        shT[c2][jl] = hi;
        slT[c2][jl] = lo;
    }
    __syncthreads();

    const int c2r = tid >> 3;  // 0..63
    const int seg = tid & 7;   // 0..7
    uint4 vh = *(const uint4*)&shT[c2r][seg * 8];
    uint4 vl = *(const uint4*)&slT[c2r][seg * 8];
    uint4 o1 = make_uint4(vh.x, vl.x, vh.y, vl.y);
    uint4 o2 = make_uint4(vh.z, vl.z, vh.w, vl.w);
    size_t wbase = ((size_t)h * 64 + c2r) * Nn + j0 + seg * 8;
    *(uint4*)(g_vi + wbase) = o1;
    *(uint4*)(g_vi + wbase + 4) = o2;
}

// ---------------------------------------------------------------------------
// Kernel 3: fused masked-softmax attention via mma.sync bf16 (split-2, 3
// products hh+hl+lh). R10 skeleton: single 55KB W+V buffer, gen reads dist
// inline (no prefetch arrays -> no spills), two barriers per tile.
// ONLY layout/tiling changed vs R10:
//   - interleaved {hi,lo} word pairs, pitch 288B: fragments load as LDS.64
//     (mma-phase LDS 160 -> 64 per warp-tile), gen stores as STS.64.
//   - m32 x n32 warp tiles (warps 0-3 cols 0-31, warps 4-7 cols 32-63):
//     B fragments shared across 2 m-tiles.
//   - V copied by cp.async (no staging registers).
// ---------------------------------------------------------------------------
#define WROW 288
#define WBYTES (128 * WROW)       // 36864
#define VBYTES (64 * WROW)        // 18432
#define SM_WSUM (WBYTES + VBYTES) // 55296
#define SM_TOTAL (SM_WSUM + 512)  // 55808

__global__ void __launch_bounds__(256, 2) att_kernel(
    const float* __restrict__ dist, const float* __restrict__ r_in,
    const int* __restrict__ locp, float* __restrict__ out) {
    extern __shared__ __align__(16) char smem[];
    const int tid = threadIdx.x;
    const int wid = tid >> 5;
    const int lid = tid & 31;
    const int h = blockIdx.y;
    const int i0 = blockIdx.x * 128;

    float th;
    {
        float sr = sinf(r_in[h]);
        float z = 0.78539816339744831f * (1.0f + sr);
        th = (float)tan((double)z);
    }

    // gen mapping (coalesced): thread (rg, kk2) covers rows rg+16l, j-pair kk2
    const int kk2 = tid & 15;
    const int rg = tid >> 4;
    float maskR[8], shiftR[8], rowacc[8];
    {
        float pct = read_pct(locp);
        float q = pct / 100.0f;
        float fidx = q * (float)(Nn - 1);
        float frac = fidx - floorf(fidx);
        float lw = 1.0f - frac;
        #pragma unroll
        for (int l = 0; l < 8; l++) {
            int i = i0 + rg + 16 * l;
            float v0 = th * g_rowstats[i];
            float v1 = th * g_rowstats[Nn + i];
            maskR[l] = v0 * lw + v1 * frac;           // jnp linear interpolation
            shiftR[l] = th * g_rowstats[2 * Nn + i];  // th * row-min (softmax shift)
            rowacc[l] = 0.0f;
        }
    }

    // mma mapping: m32 x n32 warp tiles
    const int g = lid >> 2;
    const int tq = lid & 3;
    const int wq = wid & 3;                 // row group: rows 32*wq .. +31
    const int cb = (wid >= 4) ? 32 : 0;     // col half

    // V cp.async mapping: 4 threads per V row, 64B each (row = 256B payload)
    const int vn = tid >> 2;
    const int vseg = tid & 3;
    const uint32_t* vsrc = g_vi + ((size_t)h * 64 + vn) * Nn + vseg * 16;
    const uint32_t smb = smem_u32(smem);
    const uint32_t vdst = smb + WBYTES + vn * WROW + vseg * 64;

    const float* dbase = dist + (size_t)(i0 + rg) * Nn + kk2 * 2;

    float acc[2][4][4];
    #pragma unroll
    for (int mt = 0; mt < 2; mt++)
        #pragma unroll
        for (int nt = 0; nt < 4; nt++)
            #pragma unroll
            for (int c = 0; c < 4; c++) acc[mt][nt][c] = 0.0f;

    const char* wb = smem;
    const char* vb = smem + WBYTES;

    for (int t = 0; t < Nn / 64; t++) {
        const int j0 = t * 64;
        // fire async V copy for this tile
        {
            const uint32_t* src = vsrc + j0;
            #pragma unroll
            for (int qv = 0; qv < 4; qv++)
                CP_ASYNC16(vdst + qv * 16, src + qv * 4);
            CP_COMMIT();
        }
        // generate W tile inline (reads dist directly, R10 style)
        #pragma unroll
        for (int l = 0; l < 8; l++) {
            const int il = rg + 16 * l;
            const float* dr = dbase + (size_t)(16 * l) * Nn + j0;
            float2 d0 = *(const float2*)(dr);
            float2 d1 = *(const float2*)(dr + 32);
            const float m = maskR[l], s = shiftR[l];
            float sd;
            sd = th * d0.x; float w0 = (sd <= m) ? __expf(s - sd) : 0.0f;
            sd = th * d0.y; float w1 = (sd <= m) ? __expf(s - sd) : 0.0f;
            sd = th * d1.x; float w2 = (sd <= m) ? __expf(s - sd) : 0.0f;
            sd = th * d1.y; float w3 = (sd <= m) ? __expf(s - sd) : 0.0f;
            rowacc[l] += (w0 + w1) + (w2 + w3);
            uint32_t hiA; PACK_BF16X2(hiA, w0, w1);
            float l0 = w0 - __uint_as_float(hiA << 16);
            float l1 = w1 - __uint_as_float(hiA & 0xFFFF0000u);
            uint32_t loA; PACK_BF16X2(loA, l0, l1);
            uint32_t hiB; PACK_BF16X2(hiB, w2, w3);
            float l2 = w2 - __uint_as_float(hiB << 16);
            float l3 = w3 - __uint_as_float(hiB & 0xFFFF0000u);
            uint32_t loB; PACK_BF16X2(loB, l2, l3);
            *(uint2*)(smem + il * WROW + kk2 * 8) = make_uint2(hiA, loA);
            *(uint2*)(smem + il * WROW + kk2 * 8 + 128) = make_uint2(hiB, loB);
        }
        CP_WAIT0();
        __syncthreads();

        // ---- mma sweep: 4 k-steps x (2 m-tiles x 4 n-tiles) x 3 products ----
        #pragma unroll
        for (int ks = 0; ks < 4; ks++) {
            const int ko = 64 * ks + 8 * tq;
            uint2 qa[2][4];
            #pragma unroll
            for (int mt = 0; mt < 2; mt++) {
                const char* ar = wb + (32 * wq + 16 * mt + g) * WROW + ko;
                qa[mt][0] = *(const uint2*)(ar);
                qa[mt][1] = *(const uint2*)(ar + 8 * WROW);
                qa[mt][2] = *(const uint2*)(ar + 32);
                qa[mt][3] = *(const uint2*)(ar + 8 * WROW + 32);
            }
            #pragma unroll
            for (int nt = 0; nt < 4; nt++) {
                const char* br = vb + (cb + 8 * nt + g) * WROW + ko;
                uint2 qb0 = *(const uint2*)(br);
                uint2 qb1 = *(const uint2*)(br + 32);
                #pragma unroll
                for (int mt = 0; mt < 2; mt++) {
                    MMA_BF16(acc[mt][nt][0], acc[mt][nt][1], acc[mt][nt][2], acc[mt][nt][3],
                             qa[mt][0].x, qa[mt][1].x, qa[mt][2].x, qa[mt][3].x,
                             qb0.x, qb1.x);
                    MMA_BF16(acc[mt][nt][0], acc[mt][nt][1], acc[mt][nt][2], acc[mt][nt][3],
                             qa[mt][0].x, qa[mt][1].x, qa[mt][2].x, qa[mt][3].x,
                             qb0.y, qb1.y);
                    MMA_BF16(acc[mt][nt][0], acc[mt][nt][1], acc[mt][nt][2], acc[mt][nt][3],
                             qa[mt][0].y, qa[mt][1].y, qa[mt][2].y, qa[mt][3].y,
                             qb0.x, qb1.x);
                }
            }
        }
        __syncthreads();
    }

    // ---- row softmax sums -> shared ----
    float* wsum = (float*)(smem + SM_WSUM);
    #pragma unroll
    for (int l = 0; l < 8; l++) {
        float s = rowacc[l];
        #pragma unroll
        for (int o = 8; o > 0; o >>= 1) s += __shfl_xor_sync(0xffffffffu, s, o);
        if (kk2 == 0) wsum[rg + 16 * l] = s;
    }
    __syncthreads();

    // ---- epilogue: normalize, exact gelu, write ----
    #pragma unroll
    for (int mt = 0; mt < 2; mt++) {
        const int row = 32 * wq + 16 * mt + g;
        const float invA = 1.0f / wsum[row];
        const float invB = 1.0f / wsum[row + 8];
        const int rA = i0 + row;
        const int rB = rA + 8;
        #pragma unroll
        for (int nt = 0; nt < 4; nt++) {
            const int col = cb + nt * 8 + 2 * tq;
            const int b = col >> 4;
            const int v = col & 15;
            float x;
            float2 o0, o1;
            x = acc[mt][nt][0] * invA; o0.x = 0.5f * x * (1.0f + erff(x * 0.70710678118654752f));
            x = acc[mt][nt][1] * invA; o0.y = 0.5f * x * (1.0f + erff(x * 0.70710678118654752f));
            x = acc[mt][nt][2] * invB; o1.x = 0.5f * x * (1.0f + erff(x * 0.70710678118654752f));
            x = acc[mt][nt][3] * invB; o1.y = 0.5f * x * (1.0f + erff(x * 0.70710678118654752f));
            *(float2*)(&out[((size_t)b * Nn + rA) * HV + h * Vv + v]) = o0;
            *(float2*)(&out[((size_t)b * Nn + rB) * HV + h * Vv + v]) = o1;
        }
    }
}

extern "C" void kernel_launch(void* const* d_in, const int* in_sizes, int n_in,
                              void* d_out, int out_size) {
    const float* inputs = (const float*)d_in[0];
    const float* dist   = (const float*)d_in[1];
    const float* r      = (const float*)d_in[2];
    const float* weight = (const float*)d_in[3];
    const int*   locp   = (n_in > 4) ? (const int*)d_in[4] : nullptr;
    float* out = (float*)d_out;
    (void)in_sizes; (void)out_size;

    cudaFuncSetAttribute(att_kernel, cudaFuncAttributeMaxDynamicSharedMemorySize, SM_TOTAL);

    rowstats_kernel<<<Nn, 256>>>(dist, locp);
    value_kernel<<<dim3(Nn / 64, Hh), 512>>>(inputs, weight);
    att_kernel<<<dim3(Nn / 128, Hh), 256, SM_TOTAL>>>(dist, r, locp, out);
}

// round 17
// speedup vs baseline: 1.1618x; 1.1618x over previous
#include <cuda_runtime.h>
#include <cuda_bf16.h>
#include <cstdint>

#define Nn 4096
#define Bb 4
#define Cc 128
#define Hh 8
#define Vv 16
#define HV 128

// ---------------- static device scratch ------------------------------------
__device__ __align__(16) __nv_bfloat16 g_vh[(size_t)Hh * 64 * Nn];  // value hi plane [h][c2][j]
__device__ __align__(16) __nv_bfloat16 g_vl[(size_t)Hh * 64 * Nn];  // value lo plane
__device__ float g_rowstats[3 * Nn];  // [0..N) d_lo, [N..2N) d_hi, [2N..3N) d_min

__device__ __forceinline__ float read_pct(const int* p) {
    if (!p) return 64.0f;
    int v = *p;
    if (v >= 0 && v <= 100) return (float)v;
    float f = __int_as_float(v);
    if (f >= 0.0f && f <= 100.0f) return f;
    return 64.0f;
}

// warp-level bf16 tensor-core mma (sm_80+ PTX, valid on base sm_103 target)
#define MMA_BF16(c0, c1, c2, c3, a0, a1, a2, a3, b0, b1)                      \
    asm volatile(                                                             \
        "mma.sync.aligned.m16n8k16.row.col.f32.bf16.bf16.f32 "                \
        "{%0,%1,%2,%3}, {%4,%5,%6,%7}, {%8,%9}, {%0,%1,%2,%3};"               \
        : "+f"(c0), "+f"(c1), "+f"(c2), "+f"(c3)                              \
        : "r"(a0), "r"(a1), "r"(a2), "r"(a3), "r"(b0), "r"(b1))

// ---------------------------------------------------------------------------
// Kernel 1: per row of dist: rank-k0 order statistic (radix select, exact,
// tie-safe on non-negative float bit patterns), rank-k0+1 from one extra
// pass, plus row min.  Register-resident keys (R16 version — 40us).
// ---------------------------------------------------------------------------
__global__ void __launch_bounds__(256, 1) rowstats_kernel(
    const float* __restrict__ dist, const int* __restrict__ locp) {
    __shared__ unsigned hist[256];
    __shared__ unsigned wsums[8];
    __shared__ unsigned sb[2];
    __shared__ float smin[256];
    __shared__ unsigned s_cntLE;
    __shared__ unsigned s_minAbove;

    const int row = blockIdx.x;
    const int t = threadIdx.x;

    const float* rp = dist + (size_t)row * Nn;
    unsigned key[16];
    float mn = 3.4e38f;
    #pragma unroll
    for (int it = 0; it < 16; it++) {
        float v = rp[t + 256 * it];
        key[it] = __float_as_uint(v);
        mn = fminf(mn, v);
    }
    smin[t] = mn;
    if (t == 0) { s_cntLE = 0u; s_minAbove = 0xFFFFFFFFu; }
    __syncthreads();
    for (int s = 128; s > 0; s >>= 1) {
        if (t < s) smin[t] = fminf(smin[t], smin[t + s]);
        __syncthreads();
    }

    float pct = read_pct(locp);
    float q = pct / 100.0f;
    float fidx = q * (float)(Nn - 1);
    int k0 = (int)floorf(fidx);
    if (k0 < 0) k0 = 0;
    if (k0 > Nn - 1) k0 = Nn - 1;

    int k = k0;
    unsigned prefix = 0u, pmask = 0u;
    for (int shift = 24; shift >= 0; shift -= 8) {
        hist[t] = 0u;
        __syncthreads();
        #pragma unroll
        for (int it = 0; it < 16; it++) {
            unsigned ky = key[it];
            if ((ky & pmask) == prefix)
                atomicAdd(&hist[(ky >> shift) & 255u], 1u);
        }
        __syncthreads();
        unsigned c = hist[t];
        unsigned v = c;
        #pragma unroll
        for (int o = 1; o < 32; o <<= 1) {
            unsigned u = __shfl_up_sync(0xffffffffu, v, o);
            if ((t & 31) >= o) v += u;
        }
        if ((t & 31) == 31) wsums[t >> 5] = v;
        __syncthreads();
        if (t < 8) {
            unsigned w = wsums[t];
            #pragma unroll
            for (int o = 1; o < 8; o <<= 1) {
                unsigned u = __shfl_up_sync(0xffu, w, o);
                if (t >= o) w += u;
            }
            wsums[t] = w;
        }
        __syncthreads();
        unsigned incl = v + ((t >= 32) ? wsums[(t >> 5) - 1] : 0u);
        unsigned excl = incl - c;
        if ((unsigned)k >= excl && (unsigned)k < incl) {
            sb[0] = (unsigned)t;
            sb[1] = excl;
        }
        __syncthreads();
        prefix |= sb[0] << shift;
        pmask |= 0xFFu << shift;
        k -= (int)sb[1];
        __syncthreads();
    }
    const unsigned val0 = prefix;

    {
        unsigned lcnt = 0u, lmin = 0xFFFFFFFFu;
        #pragma unroll
        for (int it = 0; it < 16; it++) {
            unsigned ky = key[it];
            if (ky <= val0) lcnt++;
            else lmin = min(lmin, ky);
        }
        #pragma unroll
        for (int o = 16; o > 0; o >>= 1) {
            lcnt += __shfl_down_sync(0xffffffffu, lcnt, o);
            lmin = min(lmin, __shfl_down_sync(0xffffffffu, lmin, o));
        }
        if ((t & 31) == 0) {
            atomicAdd(&s_cntLE, lcnt);
            atomicMin(&s_minAbove, lmin);
        }
    }
    __syncthreads();

    if (t == 0) {
        unsigned val1;
        int k1 = (k0 + 1 < Nn) ? (k0 + 1) : (Nn - 1);
        if (k1 == k0 || (unsigned)k1 < s_cntLE) val1 = val0;
        else val1 = s_minAbove;
        g_rowstats[row] = __uint_as_float(val0);
        g_rowstats[Nn + row] = __uint_as_float(val1);
        g_rowstats[2 * Nn + row] = smin[0];
    }
}

// ---------------------------------------------------------------------------
// Kernel 2: value[h][j][c2] = sum_c inputs[b,j,c]*weight[h,c,v]  (c2=b*16+v),
// split into bf16 hi/lo and written TRANSPOSED: g_vh/g_vl[h][c2][j].
// (R10 version — proven.)
// ---------------------------------------------------------------------------
__global__ void __launch_bounds__(512, 1) value_kernel(
    const float* __restrict__ inputs, const float* __restrict__ weight) {
    __shared__ float wsm[Cc * Vv];                 // 8KB
    __shared__ __nv_bfloat16 shT[64][72];          // [c2][j] hi
    __shared__ __nv_bfloat16 slT[64][72];          // [c2][j] lo
    const int h = blockIdx.y;
    const int j0 = blockIdx.x * 64;
    const int tid = threadIdx.x;

    for (int e = tid; e < Cc * Vv; e += 512) wsm[e] = weight[h * (Cc * Vv) + e];
    __syncthreads();

    const int c2 = tid & 63;
    const int jj = tid >> 6;  // 0..7
    const int b = c2 >> 4;
    const int v = c2 & 15;

    #pragma unroll
    for (int l = 0; l < 8; l++) {
        int jl = jj + l * 8;
        int j = j0 + jl;
        const float4* ip = (const float4*)(inputs + ((size_t)b * Nn + j) * Cc);
        float acc = 0.0f;
        #pragma unroll
        for (int c4 = 0; c4 < Cc / 4; c4++) {
            float4 x = ip[c4];
            acc += x.x * wsm[(c4 * 4 + 0) * Vv + v];
            acc += x.y * wsm[(c4 * 4 + 1) * Vv + v];
            acc += x.z * wsm[(c4 * 4 + 2) * Vv + v];
            acc += x.w * wsm[(c4 * 4 + 3) * Vv + v];
        }
        __nv_bfloat16 hi = __float2bfloat16(acc);
        __nv_bfloat16 lo = __float2bfloat16(acc - __bfloat162float(hi));
        shT[c2][jl] = hi;
        slT[c2][jl] = lo;
    }
    __syncthreads();

    const int c2r = tid >> 3;  // 0..63
    const int seg = tid & 7;   // 0..7
    uint4 vh = *(const uint4*)&shT[c2r][seg * 8];
    uint4 vl = *(const uint4*)&slT[c2r][seg * 8];
    size_t off = ((size_t)h * 64 + c2r) * Nn + j0 + seg * 8;
    *(uint4*)(g_vh + off) = vh;
    *(uint4*)(g_vl + off) = vl;
}

// ---------------------------------------------------------------------------
// Kernel 3: fused masked-softmax attention via mma.sync bf16 (split-2, 3
// products: hh + hl + lh; lo*lo dropped, ~2^-18 rel).
// EXACT R10 version (395.6us run): pitch-144 separate planes, warp w owns
// rows 16w..16w+15 x all 64 cols, scalar LDS.32 fragments, 2 barriers/tile.
// ---------------------------------------------------------------------------
#define PITCHB 144            // 72 bf16 per row
#define S_WH 0                // 128 rows * 144B = 18432
#define S_WL 18432
#define S_VH 36864            // 64 rows * 144B = 9216
#define S_VL 46080
#define S_WS 55296            // float wsum[128]
#define S_TOTAL 55936

__global__ void __launch_bounds__(256, 2) att_kernel(
    const float* __restrict__ dist, const float* __restrict__ r_in,
    const int* __restrict__ locp, float* __restrict__ out) {
    extern __shared__ char smem[];
    const int tid = threadIdx.x;
    const int wid = tid >> 5;
    const int lid = tid & 31;
    const int h = blockIdx.y;
    const int i0 = blockIdx.x * 128;

    // th = tan((pi/4)*(1+sin r)) with fp32-quantized argument (matches ref)
    float th;
    {
        float sr = sinf(r_in[h]);
        float z = 0.78539816339744831f * (1.0f + sr);
        th = (float)tan((double)z);
    }

    // generation mapping: thread (rg, kk2) covers rows rg+16l, j pairs kk2
    const int kk2 = tid & 15;
    const int rg = tid >> 4;
    float maskR[8], shiftR[8], rowacc[8];
    {
        float pct = read_pct(locp);
        float q = pct / 100.0f;
        float fidx = q * (float)(Nn - 1);
        float frac = fidx - floorf(fidx);
        float lw = 1.0f - frac;
        #pragma unroll
        for (int l = 0; l < 8; l++) {
            int i = i0 + rg + 16 * l;
            float v0 = th * g_rowstats[i];
            float v1 = th * g_rowstats[Nn + i];
            maskR[l] = v0 * lw + v1 * frac;           // jnp linear interpolation
            shiftR[l] = th * g_rowstats[2 * Nn + i];  // th * row-min (softmax shift)
            rowacc[l] = 0.0f;
        }
    }

    const __nv_bfloat16* vhp = g_vh + (size_t)h * 64 * Nn;
    const __nv_bfloat16* vlp = g_vl + (size_t)h * 64 * Nn;

    // mma lane mapping
    const int g = lid >> 2;   // 0..7
    const int tq = lid & 3;   // 0..3

    float acc[8][4];
    #pragma unroll
    for (int nt = 0; nt < 8; nt++)
        #pragma unroll
        for (int c = 0; c < 4; c++) acc[nt][c] = 0.0f;

    for (int t = 0; t < Nn / 64; t++) {
        const int j0 = t * 64;
        // ---- generate W tile (hi/lo bf16), accumulate row sums ----
        #pragma unroll
        for (int l = 0; l < 8; l++) {
            int row = rg + 16 * l;
            const float* dr = dist + (size_t)(i0 + row) * Nn + j0 + kk2 * 2;
            float2 dA = *(const float2*)(dr);
            float2 dB = *(const float2*)(dr + 32);
            float m = maskR[l], s = shiftR[l];
            float sd;
            sd = th * dA.x; float w00 = (sd <= m) ? __expf(s - sd) : 0.0f;
            sd = th * dA.y; float w01 = (sd <= m) ? __expf(s - sd) : 0.0f;
            sd = th * dB.x; float w10 = (sd <= m) ? __expf(s - sd) : 0.0f;
            sd = th * dB.y; float w11 = (sd <= m) ? __expf(s - sd) : 0.0f;
            rowacc[l] += (w00 + w01) + (w10 + w11);
            __nv_bfloat16 h00 = __float2bfloat16(w00);
            __nv_bfloat16 h01 = __float2bfloat16(w01);
            __nv_bfloat16 h10 = __float2bfloat16(w10);
            __nv_bfloat16 h11 = __float2bfloat16(w11);
            __nv_bfloat16 l00 = __float2bfloat16(w00 - __bfloat162float(h00));
            __nv_bfloat16 l01 = __float2bfloat16(w01 - __bfloat162float(h01));
            __nv_bfloat16 l10 = __float2bfloat16(w10 - __bfloat162float(h10));
            __nv_bfloat16 l11 = __float2bfloat16(w11 - __bfloat162float(h11));
            uint32_t ph0, pl0, ph1, pl1;
            asm("mov.b32 %0, {%1, %2};" : "=r"(ph0) : "h"(*(const uint16_t*)&h00), "h"(*(const uint16_t*)&h01));
            asm("mov.b32 %0, {%1, %2};" : "=r"(pl0) : "h"(*(const uint16_t*)&l00), "h"(*(const uint16_t*)&l01));
            asm("mov.b32 %0, {%1, %2};" : "=r"(ph1) : "h"(*(const uint16_t*)&h10), "h"(*(const uint16_t*)&h11));
            asm("mov.b32 %0, {%1, %2};" : "=r"(pl1) : "h"(*(const uint16_t*)&l10), "h"(*(const uint16_t*)&l11));
            uint32_t off0 = (uint32_t)row * PITCHB + kk2 * 4;  // k = kk2*2
            uint32_t off1 = off0 + 64;                          // k += 32
            *(uint32_t*)(smem + S_WH + off0) = ph0;
            *(uint32_t*)(smem + S_WL + off0) = pl0;
            *(uint32_t*)(smem + S_WH + off1) = ph1;
            *(uint32_t*)(smem + S_WL + off1) = pl1;
        }
        // ---- copy V tile (hi/lo), V[n][k] with 144B pitch ----
        #pragma unroll
        for (int qq = 0; qq < 2; qq++) {
            int idx = tid + qq * 256;
            int n = idx >> 3;
            int k8 = idx & 7;
            size_t srcoff = ((size_t)n * Nn + j0 + k8 * 8);
            uint32_t off = (uint32_t)n * PITCHB + k8 * 16;
            *(uint4*)(smem + S_VH + off) = *(const uint4*)(vhp + srcoff);
            *(uint4*)(smem + S_VL + off) = *(const uint4*)(vlp + srcoff);
        }
        __syncthreads();
        // ---- mma: warp wid rows 16*wid.., 8 n-tiles, 4 k-steps, 3 products ----
        #pragma unroll
        for (int ks = 0; ks < 4; ks++) {
            const int k0 = ks * 16;
            const uint32_t aoff = (uint32_t)(16 * wid + g) * PITCHB + (k0 + 2 * tq) * 2;
            uint32_t ah0 = *(const uint32_t*)(smem + S_WH + aoff);
            uint32_t ah1 = *(const uint32_t*)(smem + S_WH + aoff + 8 * PITCHB);
            uint32_t ah2 = *(const uint32_t*)(smem + S_WH + aoff + 16);
            uint32_t ah3 = *(const uint32_t*)(smem + S_WH + aoff + 8 * PITCHB + 16);
            uint32_t al0 = *(const uint32_t*)(smem + S_WL + aoff);
            uint32_t al1 = *(const uint32_t*)(smem + S_WL + aoff + 8 * PITCHB);
            uint32_t al2 = *(const uint32_t*)(smem + S_WL + aoff + 16);
            uint32_t al3 = *(const uint32_t*)(smem + S_WL + aoff + 8 * PITCHB + 16);
            #pragma unroll
            for (int nt = 0; nt < 8; nt++) {
                const uint32_t boff = (uint32_t)(8 * nt + g) * PITCHB + (k0 + 2 * tq) * 2;
                uint32_t bh0 = *(const uint32_t*)(smem + S_VH + boff);
                uint32_t bh1 = *(const uint32_t*)(smem + S_VH + boff + 16);
                uint32_t bl0 = *(const uint32_t*)(smem + S_VL + boff);
                uint32_t bl1 = *(const uint32_t*)(smem + S_VL + boff + 16);
                MMA_BF16(acc[nt][0], acc[nt][1], acc[nt][2], acc[nt][3],
                         ah0, ah1, ah2, ah3, bh0, bh1);
                MMA_BF16(acc[nt][0], acc[nt][1], acc[nt][2], acc[nt][3],
                         ah0, ah1, ah2, ah3, bl0, bl1);
                MMA_BF16(acc[nt][0], acc[nt][1], acc[nt][2], acc[nt][3],
                         al0, al1, al2, al3, bh0, bh1);
            }
        }
        __syncthreads();
    }

    // ---- row softmax sums -> shared ----
    float* wsum = (float*)(smem + S_WS);
    #pragma unroll
    for (int l = 0; l < 8; l++) {
        float s = rowacc[l];
        #pragma unroll
        for (int o = 8; o > 0; o >>= 1) s += __shfl_xor_sync(0xffffffffu, s, o);
        if (kk2 == 0) wsum[rg + 16 * l] = s;
    }
    __syncthreads();

    // ---- epilogue: normalize, exact gelu, write ----
    const int row0 = 16 * wid + g;
    const float inv0 = 1.0f / wsum[row0];
    const float inv1 = 1.0f / wsum[row0 + 8];
    #pragma unroll
    for (int nt = 0; nt < 8; nt++) {
        const int col = nt * 8 + 2 * tq;
        const int b = col >> 4;
        const int v = col & 15;
        float x;
        float2 o0, o1;
        x = acc[nt][0] * inv0; o0.x = 0.5f * x * (1.0f + erff(x * 0.70710678118654752f));
        x = acc[nt][1] * inv0; o0.y = 0.5f * x * (1.0f + erff(x * 0.70710678118654752f));
        x = acc[nt][2] * inv1; o1.x = 0.5f * x * (1.0f + erff(x * 0.70710678118654752f));
        x = acc[nt][3] * inv1; o1.y = 0.5f * x * (1.0f + erff(x * 0.70710678118654752f));
        *(float2*)(&out[((size_t)b * Nn + i0 + row0) * HV + h * Vv + col - b * 16]) = o0;
        *(float2*)(&out[((size_t)b * Nn + i0 + row0 + 8) * HV + h * Vv + col - b * 16]) = o1;
        (void)v;
    }
}

extern "C" void kernel_launch(void* const* d_in, const int* in_sizes, int n_in,
                              void* d_out, int out_size) {
    const float* inputs = (const float*)d_in[0];
    const float* dist   = (const float*)d_in[1];
    const float* r      = (const float*)d_in[2];
    const float* weight = (const float*)d_in[3];
    const int*   locp   = (n_in > 4) ? (const int*)d_in[4] : nullptr;
    float* out = (float*)d_out;
    (void)in_sizes; (void)out_size;

    cudaFuncSetAttribute(att_kernel, cudaFuncAttributeMaxDynamicSharedMemorySize, S_TOTAL);

    rowstats_kernel<<<Nn, 256>>>(dist, locp);
    value_kernel<<<dim3(Nn / 64, Hh), 512>>>(inputs, weight);
    att_kernel<<<dim3(Nn / 128, Hh), 256, S_TOTAL>>>(dist, r, locp, out);
}